// round 1
// baseline (speedup 1.0000x reference)
#include <cuda_runtime.h>

#define T_LEN   8192
#define U_DIM   64
#define I_DIM   6
#define M_OUT   16
#define UNFOLDS 6

__device__ __forceinline__ float fast_tanh(float x) {
    float y;
    asm("tanh.approx.f32 %0, %1;" : "=f"(y) : "f"(x));
    return y;
}

// One block per batch element. 256 threads: tid = j*4 + c.
//   j in [0,64): post-synaptic neuron owned by 4 lanes
//   c in [0,4):  split of the 64 pre-synaptic neurons (16 each)
__global__ void __launch_bounds__(256, 2)
ltc_seq_kernel(const float* __restrict__ x,
               const float* __restrict__ gleak, const float* __restrict__ vleak,
               const float* __restrict__ cm,
               const float* __restrict__ sigma, const float* __restrict__ mu,
               const float* __restrict__ w,     const float* __restrict__ erev,
               const float* __restrict__ ssig,  const float* __restrict__ smu,
               const float* __restrict__ sw,    const float* __restrict__ serev,
               const float* __restrict__ iw,    const float* __restrict__ ib,
               const float* __restrict__ ow,    const float* __restrict__ ob,
               float* __restrict__ out)
{
    const int b   = blockIdx.x;
    const int tid = threadIdx.x;
    const int j   = tid >> 2;
    const int c   = tid & 3;

    __shared__ float vbuf[2][U_DIM];

    // ---- per-thread recurrent synapse constants (16 pre-neurons) ----
    // sigmoid(z) = 0.5 + 0.5*tanh(z/2)
    // contribution to den: 0.5*w + 0.5*w*tanh(0.5*(v_i-mu)*sigma)
    // contribution to num: same scaled by erev (+/-1)
    float A[16], B2[16], WH[16], WE[16];
    float pWH = 0.f, pWE = 0.f;
#pragma unroll
    for (int k = 0; k < 16; ++k) {
        const int i   = c * 16 + k;
        const int idx = i * U_DIM + j;
        const float sg = sigma[idx];
        const float m  = mu[idx];
        const float wv = w[idx];
        const float ev = erev[idx];
        const float a  = 0.5f * sg;
        A [k] = a;
        B2[k] = -m * a;
        const float wh = 0.5f * wv;
        WH[k] = wh;
        WE[k] = wh * ev;
        pWH += wh;
        pWE += WE[k];
    }
    // reduce constant sums over the 4 c-lanes (full sum over i=0..63)
    pWH += __shfl_xor_sync(0xffffffffu, pWH, 1);
    pWE += __shfl_xor_sync(0xffffffffu, pWE, 1);
    pWH += __shfl_xor_sync(0xffffffffu, pWH, 2);
    pWE += __shfl_xor_sync(0xffffffffu, pWE, 2);

    // ---- sensory constants ----
    // xi = x*iw + ib ; arg = 0.5*(xi - smu)*ssig = x*(0.5*iw*ssig) + 0.5*(ib-smu)*ssig
    // full constant half-sums over all 6 sensory inputs (each thread computes, cheap, once)
    float sSWH = 0.f, sSWE = 0.f;
#pragma unroll
    for (int i = 0; i < I_DIM; ++i) {
        const float swh = 0.5f * sw[i * U_DIM + j];
        sSWH += swh;
        sSWE += swh * serev[i * U_DIM + j];
    }
    // this thread's assigned sensory inputs: c=0:{0,1} c=1:{2,3} c=2:{4} c=3:{5}
    const int  si0  = (c < 2) ? 2 * c : (2 + c);      // 0,2,4,5
    const bool has2 = (c < 2);
    const int  si1  = has2 ? (si0 + 1) : si0;
    float SA0, SB0, SW0, SE0, SA1, SB1, SW1, SE1;
    {
        float sg0 = ssig[si0 * U_DIM + j];
        SA0 = 0.5f * iw[si0] * sg0;
        SB0 = 0.5f * (ib[si0] - smu[si0 * U_DIM + j]) * sg0;
        SW0 = 0.5f * sw[si0 * U_DIM + j];
        SE0 = SW0 * serev[si0 * U_DIM + j];
        if (has2) {
            float sg1 = ssig[si1 * U_DIM + j];
            SA1 = 0.5f * iw[si1] * sg1;
            SB1 = 0.5f * (ib[si1] - smu[si1 * U_DIM + j]) * sg1;
            SW1 = 0.5f * sw[si1 * U_DIM + j];
            SE1 = SW1 * serev[si1 * U_DIM + j];
        } else {
            SA1 = 0.f; SB1 = 0.f; SW1 = 0.f; SE1 = 0.f;  // contributes tanh(0)*0 = 0
        }
    }

    // ---- per-j scalar constants ----
    const float gl  = gleak[j];
    const float vl  = vleak[j];
    const float cmt = cm[j] * (float)UNFOLDS;           // cm / (1.0/6)
    const float NC  = gl * vl + pWE + sSWE;             // constant part of num
    const float DC  = cmt + gl + pWH + sSWH;            // constant part of den
    const float owj = ow[j & (M_OUT - 1)];
    const float obj = ob[j & (M_OUT - 1)];

    // ---- init hidden state ----
    if (tid < U_DIM) { vbuf[0][tid] = 0.f; vbuf[1][tid] = 0.f; }
    __syncthreads();

    float vj = 0.f;
    int   p  = 0;
    const float* xrow = x + (size_t)b * T_LEN * I_DIM;
    float*       orow = out + (size_t)b * T_LEN * M_OUT;

    for (int t = 0; t < T_LEN; ++t) {
        // sensory partials for this step (constant across unfolds)
        const float x0 = xrow[t * I_DIM + si0];
        const float x1 = xrow[t * I_DIM + si1];
        const float s0 = fast_tanh(fmaf(x0, SA0, SB0));
        const float s1 = fast_tanh(fmaf(x1, SA1, SB1));
        const float ns = fmaf(SE0, s0, SE1 * s1);
        const float ds = fmaf(SW0, s0, SW1 * s1);

#pragma unroll
        for (int u = 0; u < UNFOLDS; ++u) {
            float nr = ns, dr = ds;
            const float* vb = vbuf[p] + c * 16;
#pragma unroll
            for (int k = 0; k < 16; ++k) {
                const float vi = vb[k];
                const float s  = fast_tanh(fmaf(vi, A[k], B2[k]));
                nr = fmaf(WE[k], s, nr);
                dr = fmaf(WH[k], s, dr);
            }
            nr += __shfl_xor_sync(0xffffffffu, nr, 1);
            dr += __shfl_xor_sync(0xffffffffu, dr, 1);
            nr += __shfl_xor_sync(0xffffffffu, nr, 2);
            dr += __shfl_xor_sync(0xffffffffu, dr, 2);
            const float num = fmaf(cmt, vj, nr + NC);
            const float den = dr + DC + 1e-8f;
            vj = __fdividef(num, den);
            if (c == 0) vbuf[p ^ 1][j] = vj;
            __syncthreads();
            p ^= 1;
        }

        if (c == 0 && j < M_OUT)
            orow[t * M_OUT + j] = fmaf(vj, owj, obj);
    }
}

extern "C" void kernel_launch(void* const* d_in, const int* in_sizes, int n_in,
                              void* d_out, int out_size)
{
    const float* x      = (const float*)d_in[0];
    const float* gleak  = (const float*)d_in[1];
    const float* vleak  = (const float*)d_in[2];
    const float* cm     = (const float*)d_in[3];
    const float* sigma  = (const float*)d_in[4];
    const float* mu     = (const float*)d_in[5];
    const float* w      = (const float*)d_in[6];
    const float* erev   = (const float*)d_in[7];
    const float* ssig   = (const float*)d_in[8];
    const float* smu    = (const float*)d_in[9];
    const float* sw     = (const float*)d_in[10];
    const float* serev  = (const float*)d_in[11];
    const float* iw     = (const float*)d_in[12];
    const float* ib     = (const float*)d_in[13];
    const float* ow     = (const float*)d_in[14];
    const float* ob     = (const float*)d_in[15];
    float* out = (float*)d_out;

    const int batch = in_sizes[0] / (T_LEN * I_DIM);  // 256
    ltc_seq_kernel<<<batch, 256>>>(x, gleak, vleak, cm, sigma, mu, w, erev,
                                   ssig, smu, sw, serev, iw, ib, ow, ob, out);
}

// round 2
// speedup vs baseline: 1.3558x; 1.3558x over previous
#include <cuda_runtime.h>

#define T_LEN   8192
#define U_DIM   64
#define I_DIM   6
#define M_OUT   16
#define UNFOLDS 6

__device__ __forceinline__ float fast_tanh(float x) {
    float y;
    asm("tanh.approx.f32 %0, %1;" : "=f"(y) : "f"(x));
    return y;
}

// One block (128 threads) per batch element. tid = j*2 + c.
//   j in [0,64): post-synaptic neuron owned by 2 lanes
//   c in [0,2):  split of the 64 pre-synaptic neurons (32 each)
__global__ void __launch_bounds__(128, 2)
ltc_seq_kernel(const float* __restrict__ x,
               const float* __restrict__ gleak, const float* __restrict__ vleak,
               const float* __restrict__ cm,
               const float* __restrict__ sigma, const float* __restrict__ mu,
               const float* __restrict__ w,     const float* __restrict__ erev,
               const float* __restrict__ ssig,  const float* __restrict__ smu,
               const float* __restrict__ sw,    const float* __restrict__ serev,
               const float* __restrict__ iw,    const float* __restrict__ ib,
               const float* __restrict__ ow,    const float* __restrict__ ob,
               float* __restrict__ out)
{
    const int b   = blockIdx.x;
    const int tid = threadIdx.x;
    const int j   = tid >> 1;
    const int c   = tid & 1;

    __shared__ float vbuf[2][U_DIM];

    // ---- per-thread recurrent synapse constants (32 pre-neurons) ----
    // sigmoid(z) = 0.5 + 0.5*tanh(z/2)
    // den contribution: 0.5*w + 0.5*w*tanh(0.5*(v_i-mu)*sigma)
    // num contribution: same scaled by erev (+/-1)
    float A[32], Bc[32], WH[32], WE[32];
    float pWH = 0.f, pWE = 0.f;
#pragma unroll
    for (int k = 0; k < 32; ++k) {
        const int i   = c * 32 + k;
        const int idx = i * U_DIM + j;
        const float sg = sigma[idx];
        const float m  = mu[idx];
        const float wv = w[idx];
        const float ev = erev[idx];
        const float a  = 0.5f * sg;
        A [k] = a;
        Bc[k] = -m * a;
        const float wh = 0.5f * wv;
        WH[k] = wh;
        WE[k] = wh * ev;
        pWH += wh;
        pWE += WE[k];
    }
    // full sums over i=0..63 (combine the two c-lanes)
    pWH += __shfl_xor_sync(0xffffffffu, pWH, 1);
    pWE += __shfl_xor_sync(0xffffffffu, pWE, 1);

    // ---- sensory constants ----
    // xi = x*iw + ib ; arg = 0.5*(xi - smu)*ssig = x*(0.5*iw*ssig) + 0.5*(ib-smu)*ssig
    float sSWH = 0.f, sSWE = 0.f;
#pragma unroll
    for (int i = 0; i < I_DIM; ++i) {
        const float swh = 0.5f * sw[i * U_DIM + j];
        sSWH += swh;
        sSWE += swh * serev[i * U_DIM + j];
    }
    // this thread's 3 sensory inputs: c*3 + {0,1,2}
    float SA[3], SB[3], SWc[3], SE[3];
#pragma unroll
    for (int m = 0; m < 3; ++m) {
        const int si = c * 3 + m;
        const float sg = ssig[si * U_DIM + j];
        SA [m] = 0.5f * iw[si] * sg;
        SB [m] = 0.5f * (ib[si] - smu[si * U_DIM + j]) * sg;
        SWc[m] = 0.5f * sw[si * U_DIM + j];
        SE [m] = SWc[m] * serev[si * U_DIM + j];
    }

    // ---- per-j scalar constants ----
    const float gl  = gleak[j];
    const float vl  = vleak[j];
    const float cmt = cm[j] * (float)UNFOLDS;           // cm / (1.0/6)
    // half of the uniform constants per lane so the 2-lane reduction counts them once
    const float hNC = 0.5f * (gl * vl + pWE + sSWE);
    const float hDC = 0.5f * (cmt + gl + pWH + sSWH + 1e-8f);
    const float owj = ow[j & (M_OUT - 1)];
    const float obj = ob[j & (M_OUT - 1)];

    // ---- init hidden state ----
    if (tid < U_DIM) { vbuf[0][tid] = 0.f; vbuf[1][tid] = 0.f; }
    __syncthreads();

    float vj = 0.f;
    const float* xrow = x + (size_t)b * T_LEN * I_DIM + c * 3;
    float*       orow = out + (size_t)b * T_LEN * M_OUT;

    // prefetch x for t=0
    float xr0 = __ldg(xrow + 0);
    float xr1 = __ldg(xrow + 1);
    float xr2 = __ldg(xrow + 2);

    for (int t = 0; t < T_LEN; ++t) {
        // sensory partials for this step (constant across unfolds), lane-partial
        const float s0 = fast_tanh(fmaf(xr0, SA[0], SB[0]));
        const float s1 = fast_tanh(fmaf(xr1, SA[1], SB[1]));
        const float s2 = fast_tanh(fmaf(xr2, SA[2], SB[2]));
        const float ns = fmaf(SE[0], s0, fmaf(SE[1], s1, fmaf(SE[2], s2, hNC)));
        const float ds = fmaf(SWc[0], s0, fmaf(SWc[1], s1, fmaf(SWc[2], s2, hDC)));

        // prefetch x for next step (hides LDG latency under the 6 unfolds)
        {
            const int tn = (t + 1 < T_LEN) ? (t + 1) : t;
            const float* xn = xrow + (size_t)tn * I_DIM;
            xr0 = __ldg(xn + 0);
            xr1 = __ldg(xn + 1);
            xr2 = __ldg(xn + 2);
        }

#pragma unroll
        for (int u = 0; u < UNFOLDS; ++u) {
            float nr = ns, dr = ds;
            const float* vb = vbuf[u & 1] + c * 32;
#pragma unroll
            for (int k = 0; k < 32; ++k) {
                const float s = fast_tanh(fmaf(vb[k], A[k], Bc[k]));
                nr = fmaf(WE[k], s, nr);
                dr = fmaf(WH[k], s, dr);
            }
            nr += __shfl_xor_sync(0xffffffffu, nr, 1);
            dr += __shfl_xor_sync(0xffffffffu, dr, 1);
            const float num = fmaf(cmt, vj, nr);
            vj = __fdividef(num, dr);
            if (c == 0) vbuf[(u & 1) ^ 1][j] = vj;
            __syncthreads();
        }

        if (c == 0 && j < M_OUT)
            orow[t * M_OUT + j] = fmaf(vj, owj, obj);
    }
}

extern "C" void kernel_launch(void* const* d_in, const int* in_sizes, int n_in,
                              void* d_out, int out_size)
{
    const float* x      = (const float*)d_in[0];
    const float* gleak  = (const float*)d_in[1];
    const float* vleak  = (const float*)d_in[2];
    const float* cm     = (const float*)d_in[3];
    const float* sigma  = (const float*)d_in[4];
    const float* mu     = (const float*)d_in[5];
    const float* w      = (const float*)d_in[6];
    const float* erev   = (const float*)d_in[7];
    const float* ssig   = (const float*)d_in[8];
    const float* smu    = (const float*)d_in[9];
    const float* sw     = (const float*)d_in[10];
    const float* serev  = (const float*)d_in[11];
    const float* iw     = (const float*)d_in[12];
    const float* ib     = (const float*)d_in[13];
    const float* ow     = (const float*)d_in[14];
    const float* ob     = (const float*)d_in[15];
    float* out = (float*)d_out;

    const int batch = in_sizes[0] / (T_LEN * I_DIM);  // 256
    ltc_seq_kernel<<<batch, 128>>>(x, gleak, vleak, cm, sigma, mu, w, erev,
                                   ssig, smu, sw, serev, iw, ib, ow, ob, out);
}